// round 16
// baseline (speedup 1.0000x reference)
#include <cuda_runtime.h>
#include <cuda_fp16.h>
#include <cstdint>

#define NB      4
#define NNODES  50000
#define DIN     128
#define DOUT    64
#define NEDGES  800000
#define MTOTAL  (NB * NNODES)

#define XH_STRIDE 136                               // halves per row; conflict-free frags
#define GEMM_SMEM (64 * XH_STRIDE * 2)              // 17408 B (64-row tile)
#define SCAN_TILE 4096                              // 1 << 12
#define NSCAN_BLOCKS ((NNODES + SCAN_TILE - 1) / SCAN_TILE)   // 13

// ---------------- device scratch ----------------
__device__ __half g_preh[MTOTAL * DOUT];          // [b][node][dout] fp16
__device__ unsigned int g_wfh[8 * 4 * 32 * 4];    // W fp16 fragments: [kk16][jpg][lane][4]
__device__ int   g_counts[NNODES];
__device__ int   g_offs[NNODES + 1];              // local inclusive offsets
__device__ int   g_cursor[NNODES];                // local exclusive starts
__device__ int   g_bsum[NSCAN_BLOCKS];            // RAW block totals (scan2 folded into consumers)
__device__ int2  g_edge[NEDGES];                  // {col, float_as_int(val)}

// ---------------- mma helper: m16n8k16 fp16 in, fp32 accum ----------------
__device__ __forceinline__ void mma_f16(float4& d,
                                        unsigned int a0, unsigned int a1,
                                        unsigned int a2, unsigned int a3,
                                        unsigned int b0, unsigned int b1) {
    asm("mma.sync.aligned.m16n8k16.row.col.f32.f16.f16.f32 "
        "{%0,%1,%2,%3}, {%4,%5,%6,%7}, {%8,%9}, {%0,%1,%2,%3};"
        : "+f"(d.x), "+f"(d.y), "+f"(d.z), "+f"(d.w)
        : "r"(a0), "r"(a1), "r"(a2), "r"(a3), "r"(b0), "r"(b1));
}
__device__ __forceinline__ unsigned int h2u(__half2 h) {
    return *reinterpret_cast<unsigned int*>(&h);
}

// ---------------- CSR build ----------------
__global__ void hist_kernel(const int* __restrict__ erows) {
    int e0 = (blockIdx.x * 256 + threadIdx.x) * 8;
    if (e0 + 7 < NEDGES) {
        int4 r0 = *reinterpret_cast<const int4*>(erows + e0);
        int4 r1 = *reinterpret_cast<const int4*>(erows + e0 + 4);
        atomicAdd(&g_counts[r0.x], 1);
        atomicAdd(&g_counts[r0.y], 1);
        atomicAdd(&g_counts[r0.z], 1);
        atomicAdd(&g_counts[r0.w], 1);
        atomicAdd(&g_counts[r1.x], 1);
        atomicAdd(&g_counts[r1.y], 1);
        atomicAdd(&g_counts[r1.z], 1);
        atomicAdd(&g_counts[r1.w], 1);
    } else {
        for (int e = e0; e < NEDGES; e++) atomicAdd(&g_counts[erows[e]], 1);
    }
}

__global__ void scan1_kernel() {
    __shared__ int wsum[32];
    int tid = threadIdx.x, lane = tid & 31, wid = tid >> 5;
    int base = blockIdx.x * SCAN_TILE;

    int i0 = base + tid * 4;
    int v0 = (i0 + 0 < NNODES) ? g_counts[i0 + 0] : 0;
    int v1 = (i0 + 1 < NNODES) ? g_counts[i0 + 1] : 0;
    int v2 = (i0 + 2 < NNODES) ? g_counts[i0 + 2] : 0;
    int v3 = (i0 + 3 < NNODES) ? g_counts[i0 + 3] : 0;
    int c0 = v0, c1 = c0 + v1, c2 = c1 + v2, c3 = c2 + v3;

    int s = c3;
    #pragma unroll
    for (int off = 1; off < 32; off <<= 1) {
        int n = __shfl_up_sync(0xffffffffu, s, off);
        if (lane >= off) s += n;
    }
    if (lane == 31) wsum[wid] = s;
    __syncthreads();
    if (wid == 0) {
        int t = wsum[lane];
        #pragma unroll
        for (int off = 1; off < 32; off <<= 1) {
            int n = __shfl_up_sync(0xffffffffu, t, off);
            if (lane >= off) t += n;
        }
        wsum[lane] = t;
        if (lane == 31) g_bsum[blockIdx.x] = t;   // RAW total
    }
    __syncthreads();

    int excl = (wid > 0 ? wsum[wid - 1] : 0) + (s - c3);
    if (i0 + 0 < NNODES) { g_offs[i0 + 1] = excl + c0; g_cursor[i0 + 0] = excl; }
    if (i0 + 1 < NNODES) { g_offs[i0 + 2] = excl + c1; g_cursor[i0 + 1] = excl + c0; }
    if (i0 + 2 < NNODES) { g_offs[i0 + 3] = excl + c2; g_cursor[i0 + 2] = excl + c1; }
    if (i0 + 3 < NNODES) { g_offs[i0 + 4] = excl + c3; g_cursor[i0 + 3] = excl + c2; }
    if (blockIdx.x == 0 && tid == 0) g_offs[0] = 0;
}

// per-block smem prefix of the 13 block totals (replaces scan2)
__device__ __forceinline__ void load_bsum_prefix(int* sbx) {
    if (threadIdx.x < NSCAN_BLOCKS) sbx[threadIdx.x] = g_bsum[threadIdx.x];
    __syncthreads();
    if (threadIdx.x == 0) {
        int s = 0;
        #pragma unroll
        for (int i = 0; i < NSCAN_BLOCKS; i++) { int v = sbx[i]; sbx[i] = s; s += v; }
    }
    __syncthreads();
}

// scatter: 8 edges/thread, vectorized loads, scan2+scan3 folded in
__global__ void scatter_kernel(const int* __restrict__ erows,
                               const int* __restrict__ ecols,
                               const float* __restrict__ evals) {
    __shared__ int sbx[NSCAN_BLOCKS + 3];
    load_bsum_prefix(sbx);

    int e0 = (blockIdx.x * 256 + threadIdx.x) * 8;
    #pragma unroll
    for (int u = 0; u < 8; u++) {
        int e = e0 + u;
        if (e < NEDGES) {
            int r = erows[e];
            int pos = atomicAdd(&g_cursor[r], 1) + sbx[r >> 12];
            g_edge[pos] = make_int2(ecols[e], __float_as_int(evals[e]));
        }
    }
}

// ---------------- W fragment prep: fp16, m16n8k16 B layout, paired j ----------------
__global__ void wfrag_kernel(const float* __restrict__ w) {
    int i = blockIdx.x * 256 + threadIdx.x;   // 0..4095
    int q    = i & 3;
    int ln   = (i >> 2) & 31;
    int jpg  = (i >> 7) & 3;
    int kk16 = i >> 9;
    int j    = jpg * 2 + (q >> 1);
    int br   = q & 1;
    int g    = ln >> 2;
    int tig  = ln & 3;
    int k0   = kk16 * 16 + tig * 2 + br * 8;
    int c    = j * 8 + g;
    g_wfh[i] = h2u(__floats2half2_rn(w[k0 * DOUT + c], w[(k0 + 1) * DOUT + c]));
}

// ---------------- GEMM: fp16 m16n8k16, 128-thr CTA, 64-row tile, 8 CTAs/SM ----------------
// 4 warps; warp tile 16(M) x 64(N). Fine CTA granularity staggers load phases
// across 8 CTAs/SM to keep DRAM saturated.
__global__ __launch_bounds__(128, 8) void gemm_kernel(const float* __restrict__ x) {
    extern __shared__ __half xs[];   // [64][136] fp16

    int t = threadIdx.x, lane = t & 31, wid = t >> 5;
    int g   = lane >> 2;
    int tig = lane & 3;

    size_t mblk = (size_t)blockIdx.x * 64;

    // stage 64 rows x 128 k as fp16: 16 float4 loads per thread
    #pragma unroll
    for (int it = 0; it < 16; it++) {
        int i   = t + it * 128;      // 0..2047
        int row = i >> 5;            // 0..63
        int q   = i & 31;
        size_t m = mblk + row;
        if (m >= MTOTAL) m = MTOTAL - 1;
        float4 v = *reinterpret_cast<const float4*>(x + m * DIN + q * 4);
        uint2 h;
        h.x = h2u(__floats2half2_rn(v.x, v.y));
        h.y = h2u(__floats2half2_rn(v.z, v.w));
        *reinterpret_cast<uint2*>(&xs[row * XH_STRIDE + q * 4]) = h;
    }
    __syncthreads();

    int mw = wid * 16;               // warp rows mw..mw+15
    int rA = mw + g;

    float4 acc[8] = {};
    const uint4* wf4 = reinterpret_cast<const uint4*>(g_wfh);

    #pragma unroll
    for (int kk16 = 0; kk16 < 8; kk16++) {
        int klo = kk16 * 16 + tig * 2;

        unsigned int a0 = *reinterpret_cast<const unsigned int*>(&xs[(rA    ) * XH_STRIDE + klo]);
        unsigned int a1 = *reinterpret_cast<const unsigned int*>(&xs[(rA + 8) * XH_STRIDE + klo]);
        unsigned int a2 = *reinterpret_cast<const unsigned int*>(&xs[(rA    ) * XH_STRIDE + klo + 8]);
        unsigned int a3 = *reinterpret_cast<const unsigned int*>(&xs[(rA + 8) * XH_STRIDE + klo + 8]);

        #pragma unroll
        for (int jp = 0; jp < 4; jp++) {
            uint4 bb = __ldg(&wf4[(kk16 * 4 + jp) * 32 + lane]);
            mma_f16(acc[jp * 2],     a0, a1, a2, a3, bb.x, bb.y);
            mma_f16(acc[jp * 2 + 1], a0, a1, a2, a3, bb.z, bb.w);
        }
    }

    size_t mr0 = mblk + mw + g;
    size_t mr1 = mr0 + 8;
    bool v0 = mr0 < MTOTAL;
    bool v1 = mr1 < MTOTAL;
    #pragma unroll
    for (int j = 0; j < 8; j++) {
        __half2 h0 = __floats2half2_rn(acc[j].x, acc[j].y);
        __half2 h1 = __floats2half2_rn(acc[j].z, acc[j].w);
        int col = j * 8 + tig * 2;
        if (v0) *reinterpret_cast<__half2*>(g_preh + mr0 * DOUT + col) = h0;
        if (v1) *reinterpret_cast<__half2*>(g_preh + mr1 * DOUT + col) = h1;
    }
}

// ---------------- aggregation: warp/row, 4-edge unroll, bsum prefix in smem ----------------
__device__ __forceinline__ void acc_edge(const __half2* __restrict__ p2,
                                         size_t bstride, int lane, int2 e,
                                         float2& a0, float2& a1,
                                         float2& a2, float2& a3) {
    float v = __int_as_float(e.y);
    size_t b = (size_t)e.x * (DOUT / 2) + lane;
    float2 f;
    f = __half22float2(p2[b]);               a0.x += v * f.x; a0.y += v * f.y;
    f = __half22float2(p2[b +     bstride]); a1.x += v * f.x; a1.y += v * f.y;
    f = __half22float2(p2[b + 2 * bstride]); a2.x += v * f.x; a2.y += v * f.y;
    f = __half22float2(p2[b + 3 * bstride]); a3.x += v * f.x; a3.y += v * f.y;
}

__global__ void aggregate_kernel(float* __restrict__ out) {
    __shared__ int sbx[NSCAN_BLOCKS + 3];
    load_bsum_prefix(sbx);

    int gwarp = (blockIdx.x * blockDim.x + threadIdx.x) >> 5;
    int lane  = threadIdx.x & 31;
    if (gwarp >= NNODES) return;

    int sbPrev = (gwarp > 0) ? ((gwarp - 1) >> 12) : 0;
    int start = g_offs[gwarp]     + sbx[sbPrev];
    int end   = g_offs[gwarp + 1] + sbx[gwarp >> 12];

    float2 a0 = make_float2(0.f, 0.f), a1 = a0, a2 = a0, a3 = a0;
    const __half2* p2 = reinterpret_cast<const __half2*>(g_preh);
    const size_t bstride = (size_t)NNODES * (DOUT / 2);

    int i = start;
    for (; i + 3 < end; i += 4) {
        int2 e0 = g_edge[i];
        int2 e1 = g_edge[i + 1];
        int2 e2 = g_edge[i + 2];
        int2 e3 = g_edge[i + 3];
        acc_edge(p2, bstride, lane, e0, a0, a1, a2, a3);
        acc_edge(p2, bstride, lane, e1, a0, a1, a2, a3);
        acc_edge(p2, bstride, lane, e2, a0, a1, a2, a3);
        acc_edge(p2, bstride, lane, e3, a0, a1, a2, a3);
    }
    for (; i < end; i++) {
        int2 e0 = g_edge[i];
        acc_edge(p2, bstride, lane, e0, a0, a1, a2, a3);
    }

    float2* o2 = reinterpret_cast<float2*>(out);
    size_t ob = (size_t)gwarp * (DOUT / 2) + lane;
    o2[ob]               = make_float2(fmaxf(a0.x, 0.f), fmaxf(a0.y, 0.f));
    o2[ob +     bstride] = make_float2(fmaxf(a1.x, 0.f), fmaxf(a1.y, 0.f));
    o2[ob + 2 * bstride] = make_float2(fmaxf(a2.x, 0.f), fmaxf(a2.y, 0.f));
    o2[ob + 3 * bstride] = make_float2(fmaxf(a3.x, 0.f), fmaxf(a3.y, 0.f));
}

// ---------------- launch ----------------
extern "C" void kernel_launch(void* const* d_in, const int* in_sizes, int n_in,
                              void* d_out, int out_size) {
    const float* x     = (const float*)d_in[0];
    const float* w     = (const float*)d_in[1];
    const float* evals = (const float*)d_in[2];
    const int*   erows = (const int*)  d_in[3];
    const int*   ecols = (const int*)  d_in[4];
    float* out = (float*)d_out;

    (void)in_sizes; (void)n_in; (void)out_size;

    cudaFuncSetAttribute(gemm_kernel,
                         cudaFuncAttributeMaxDynamicSharedMemorySize, GEMM_SMEM);

    void* counts_ptr = nullptr;
    cudaGetSymbolAddress(&counts_ptr, g_counts);
    cudaMemsetAsync(counts_ptr, 0, NNODES * sizeof(int), 0);

    hist_kernel<<<(NEDGES / 8 + 255) / 256, 256>>>(erows);           // idx 0
    wfrag_kernel<<<16, 256>>>(w);                                    // idx 1
    scan1_kernel<<<NSCAN_BLOCKS, 1024>>>();                          // idx 2
    gemm_kernel<<<(MTOTAL + 63) / 64, 128, GEMM_SMEM>>>(x);          // idx 3 <- profiled
    scatter_kernel<<<(NEDGES / 8 + 255) / 256, 256>>>(erows, ecols, evals);
    aggregate_kernel<<<(NNODES * 32 + 255) / 256, 256>>>(out);
}